// round 14
// baseline (speedup 1.0000x reference)
#include <cuda_runtime.h>
#include <cstdint>

// out[b,h,i,j] = mask[b,h,i,j] - |slope[h] * (i - j)|
// B=2, NH=16, L=2048 -> 134,217,728 fp32
// slope[h] = 2^(-0.5*(h+1)) for NH=16
//
// Pure HBM-streaming kernel at the measured LTS/HBM ceiling (~86% of 8 TB/s,
// 1:1 R/W stream). This round: Blackwell 256-bit ld/st (v8.b32, sm_100+) to
// halve LDG/STG instruction and L1tex-wavefront count per byte. All other
// config = proven best point: 64 B/thread, 256 thr, exact grid, per-block h
// hoist, bit-exact slopes (rel_err 0.0).
//
// elems/block = 256 thr * 2 v8 * 8 = 4096 = 2^12 -> elem_base = bid << 12,
// h = (elem_base >> 22) & 15 = (bid >> 10) & 15.

static constexpr int L_LOG2 = 11;                   // L = 2048
static constexpr unsigned N_V8 = 1u << 24;          // 2^27 elems / 8
static constexpr int THREADS = 256;
static constexpr int V8_PER_THREAD = 2;             // 2 x 32 B = 64 B/thread
// N_V8 / (THREADS * V8_PER_THREAD) = 2^24 / 2^9 = 32768 blocks, no tail

__device__ __forceinline__ float alibi_slope(int h) {
    // slope = 2^(-0.5*(h+1)), bit-exact vs fp32 reference.
    int hp1 = h + 1;
    int e = hp1 >> 1;                                       // 0..8
    float p = __uint_as_float((unsigned)(127 - e) << 23);   // exact 2^-e
    return (hp1 & 1) ? p * 0.70710678118654752f : p;        // * sqrt(1/2) if odd
}

__device__ __forceinline__ void ldg256(const float* p, float r[8]) {
    unsigned u0,u1,u2,u3,u4,u5,u6,u7;
    asm volatile("ld.global.v8.b32 {%0,%1,%2,%3,%4,%5,%6,%7}, [%8];"
        : "=r"(u0),"=r"(u1),"=r"(u2),"=r"(u3),
          "=r"(u4),"=r"(u5),"=r"(u6),"=r"(u7)
        : "l"(p));
    r[0]=__uint_as_float(u0); r[1]=__uint_as_float(u1);
    r[2]=__uint_as_float(u2); r[3]=__uint_as_float(u3);
    r[4]=__uint_as_float(u4); r[5]=__uint_as_float(u5);
    r[6]=__uint_as_float(u6); r[7]=__uint_as_float(u7);
}

__device__ __forceinline__ void stg256(float* p, const float r[8]) {
    asm volatile("st.global.cs.v8.b32 [%0], {%1,%2,%3,%4,%5,%6,%7,%8};"
        :: "l"(p),
           "r"(__float_as_uint(r[0])), "r"(__float_as_uint(r[1])),
           "r"(__float_as_uint(r[2])), "r"(__float_as_uint(r[3])),
           "r"(__float_as_uint(r[4])), "r"(__float_as_uint(r[5])),
           "r"(__float_as_uint(r[6])), "r"(__float_as_uint(r[7]))
        : "memory");
}

__global__ __launch_bounds__(THREADS)
void alibi_kernel(const float* __restrict__ mask, float* __restrict__ out) {
    // v8-slot index of this thread's first chunk
    const unsigned w0 = blockIdx.x * (THREADS * V8_PER_THREAD) + threadIdx.x;

    // h and slope are uniform across the block
    const int h = (int)((blockIdx.x >> 10) & 15u);
    const float slope = alibi_slope(h);

    // front-batched independent 256-bit loads (2 x 32 B outstanding)
    float m[V8_PER_THREAD][8];
#pragma unroll
    for (int k = 0; k < V8_PER_THREAD; k++)
        ldg256(mask + (size_t)(w0 + k * THREADS) * 8, m[k]);

#pragma unroll
    for (int k = 0; k < V8_PER_THREAD; k++) {
        unsigned idx = (w0 + (unsigned)(k * THREADS)) << 3;   // elem index < 2^27
        int j = (int)(idx & ((1u << L_LOG2) - 1u));           // 8 consecutive j's
        int i = (int)((idx >> L_LOG2) & ((1u << L_LOG2) - 1u));
        float base = (float)(i - j);

        float r[8];
#pragma unroll
        for (int e = 0; e < 8; e++)
            r[e] = m[k][e] - fabsf(slope * (base - (float)e));

        stg256(out + (size_t)(w0 + k * THREADS) * 8, r);
    }
}

extern "C" void kernel_launch(void* const* d_in, const int* in_sizes, int n_in,
                              void* d_out, int out_size) {
    const float* mask = (const float*)d_in[0];
    float* out = (float*)d_out;

    const unsigned blocks = N_V8 / (THREADS * V8_PER_THREAD);   // 32768
    alibi_kernel<<<blocks, THREADS>>>(mask, out);
}

// round 15
// speedup vs baseline: 1.0059x; 1.0059x over previous
#include <cuda_runtime.h>
#include <cstdint>

// out[b,h,i,j] = mask[b,h,i,j] - |slope[h] * (i - j)|
// B=2, NH=16, L=2048 -> 134,217,728 fp32 = 33,554,432 float4
// slope[h] = 2^(-0.5*(h+1)) for NH=16
//
// FINAL. Pure HBM-streaming kernel: 512 MiB read + 512 MiB write (compulsory
// minimum; bias register-computed, never materialized). Thirteen benches over
// {MLP 1/4/8} x {256/512/1024 thr} x {16B/32B vectors} x {cs/wt} x
// {occ 49-79%} all plateau at 85.0-86.7% of 8 TB/s (148.4-153.4 us ncu) —
// the path-independent LTS/HBM ceiling for a 1:1 R/W stream (~6300 B/cyc;
// LDG.cv == TMA at this cap per the B300 model). SM pipes <25% busy.
// Config: best measured point — MLP_p1=4, 256 thr, regs 32, 8 CTAs/SM,
// exact grid (no tail/bounds), bit-exact slopes (rel_err = 0.0).

static constexpr int L_LOG2 = 11;                  // L = 2048
static constexpr int NH_MASK = 15;                 // NH = 16
static constexpr unsigned N_VEC = 1u << 25;        // 2^27 elems / 4
static constexpr int THREADS = 256;
static constexpr int VPT = 4;                      // float4 per thread (64 B)
// N_VEC / (THREADS*VPT) = 32768 exactly -> no tail, no bounds check

__device__ __forceinline__ float alibi_slope(int h) {
    // slope = 2^(-0.5*(h+1)), bit-exact vs the fp32 reference values.
    int hp1 = h + 1;
    int e = hp1 >> 1;                                       // 0..8
    float p = __uint_as_float((unsigned)(127 - e) << 23);   // exact 2^-e
    return (hp1 & 1) ? p * 0.70710678118654752f : p;        // * sqrt(1/2) if odd
}

__global__ __launch_bounds__(THREADS)
void alibi_kernel(const float4* __restrict__ mask, float4* __restrict__ out) {
    const unsigned v0 = blockIdx.x * (THREADS * VPT) + threadIdx.x;

    // front-batched independent loads (MLP_p1 = 4), immediate offsets off one base
    const float4* __restrict__ src = mask + v0;
    float4 m[VPT];
#pragma unroll
    for (int k = 0; k < VPT; k++)
        m[k] = __ldcs(src + k * THREADS);

    float4* __restrict__ dst = out + v0;
#pragma unroll
    for (int k = 0; k < VPT; k++) {
        unsigned idx = (v0 + (unsigned)(k * THREADS)) << 2;   // elem index < 2^27
        int j = (int)(idx & ((1u << L_LOG2) - 1u));
        int i = (int)((idx >> L_LOG2) & ((1u << L_LOG2) - 1u));
        int h = (int)((idx >> (2 * L_LOG2)) & NH_MASK);

        float slope = alibi_slope(h);
        float base  = (float)(i - j);

        float4 r;
        r.x = m[k].x - fabsf(slope * (base - 0.0f));
        r.y = m[k].y - fabsf(slope * (base - 1.0f));
        r.z = m[k].z - fabsf(slope * (base - 2.0f));
        r.w = m[k].w - fabsf(slope * (base - 3.0f));
        __stcs(dst + k * THREADS, r);
    }
}

extern "C" void kernel_launch(void* const* d_in, const int* in_sizes, int n_in,
                              void* d_out, int out_size) {
    const float4* mask = (const float4*)d_in[0];
    float4* out = (float4*)d_out;

    const unsigned blocks = N_VEC / (THREADS * VPT);   // 32768
    alibi_kernel<<<blocks, THREADS>>>(mask, out);
}